// round 9
// baseline (speedup 1.0000x reference)
#include <cuda_runtime.h>
#include <cuda_bf16.h>
#include <stdint.h>

#define M_SIZE 4096
#define NMODES 128
#define BATCH  32
#define CH     256
#define NROWS  (BATCH*CH)   // 8192
#define NC     (2*NMODES)   // 256

// ---------------- device scratch (allocation-free globals) ----------------
__device__ __nv_bfloat16 g_basis_h[(size_t)M_SIZE*NC];   // [t][c]  (inv B)
__device__ __nv_bfloat16 g_basis_l[(size_t)M_SIZE*NC];
__device__ __nv_bfloat16 g_basisT_h[(size_t)NC*M_SIZE];  // [c][t]  (fwd B)
__device__ __nv_bfloat16 g_basisT_l[(size_t)NC*M_SIZE];
__device__ __nv_bfloat16 g_x_h[(size_t)NROWS*M_SIZE];    // x split planes [row][k]
__device__ __nv_bfloat16 g_x_l[(size_t)NROWS*M_SIZE];
__device__ __nv_bfloat16 g_xT_h[(size_t)NC*NROWS];       // xft planes [c][row]
__device__ __nv_bfloat16 g_xT_l[(size_t)NC*NROWS];
// weight planes [m][o][i] bf16 hi/lo
__device__ __nv_bfloat16 gWre_h[(size_t)NMODES*CH*CH], gWre_l[(size_t)NMODES*CH*CH];
__device__ __nv_bfloat16 gWim_h[(size_t)NMODES*CH*CH], gWim_l[(size_t)NMODES*CH*CH];
__device__ __nv_bfloat16 g_oft_h[(size_t)NROWS*NC];      // [row][c] scaled
__device__ __nv_bfloat16 g_oft_l[(size_t)NROWS*NC];

// ---------------- helpers ----------------
__device__ __forceinline__ uint32_t smem_u32(const void* p) {
    uint32_t a;
    asm("{ .reg .u64 t; cvta.to.shared.u64 t, %1; cvt.u32.u64 %0, t; }" : "=r"(a) : "l"(p));
    return a;
}
#define SW(o) ((uint32_t)(o) ^ ((((uint32_t)(o)) >> 3) & 0x70))

#define CP16(d, s)  asm volatile("cp.async.cg.shared.global [%0], [%1], 16;" :: "r"(d), "l"(s))
#define CP_COMMIT() asm volatile("cp.async.commit_group;")
#define CP_WAIT0()  asm volatile("cp.async.wait_group 0;")

#define LDSM4(R, addr) \
    asm volatile("ldmatrix.sync.aligned.m8n8.x4.shared.b16 {%0,%1,%2,%3}, [%4];" \
        : "=r"((R)[0]), "=r"((R)[1]), "=r"((R)[2]), "=r"((R)[3]) : "r"(addr))

#define MMA4(C, A, b0, b1) \
    asm volatile("mma.sync.aligned.m16n8k16.row.col.f32.bf16.bf16.f32 " \
        "{%0,%1,%2,%3},{%4,%5,%6,%7},{%8,%9},{%0,%1,%2,%3};" \
        : "+f"((C)[0]), "+f"((C)[1]), "+f"((C)[2]), "+f"((C)[3]) \
        : "r"((A)[0]), "r"((A)[1]), "r"((A)[2]), "r"((A)[3]), "r"(b0), "r"(b1))

__device__ __forceinline__ void split_bf16(float v, __nv_bfloat16& h, __nv_bfloat16& l) {
    h = __float2bfloat16(v);
    l = __float2bfloat16(v - __bfloat162float(h));
}
__device__ __forceinline__ uint2 pack4(__nv_bfloat16 a, __nv_bfloat16 b,
                                       __nv_bfloat16 c, __nv_bfloat16 d) {
    __nv_bfloat162 p = __halves2bfloat162(a, b), q = __halves2bfloat162(c, d);
    return make_uint2(*(uint32_t*)&p, *(uint32_t*)&q);
}

// smem plane offsets for fwd/inv (per 48KB buffer: A 64rows, B 128rows)
#define P_AH 0
#define P_AL 8192
#define P_BH 16384
#define P_BL 32768
#define BUFB 49152
#define SMEM_GEMM (2*BUFB)   // 96KB -> 2 CTAs/SM

// ---------------------------------------------------------------------------
// x split prepass: fp32 -> bf16 hi/lo planes, fully coalesced.
// ---------------------------------------------------------------------------
__global__ void __launch_bounds__(256) k_xsplit(const float* __restrict__ x) {
    size_t idx = ((size_t)blockIdx.x * 256 + threadIdx.x) * 4;
    float4 v = *(const float4*)&x[idx];
    __nv_bfloat16 h0,l0,h1,l1,h2,l2,h3,l3;
    split_bf16(v.x,h0,l0); split_bf16(v.y,h1,l1);
    split_bf16(v.z,h2,l2); split_bf16(v.w,h3,l3);
    *(uint2*)&g_x_h[idx] = pack4(h0,h1,h2,h3);
    *(uint2*)&g_x_l[idx] = pack4(l0,l1,l2,l3);
}

// ---------------------------------------------------------------------------
// Basis tables
// ---------------------------------------------------------------------------
__global__ void k_basis_a() {   // [t][c]
    int idx = blockIdx.x * blockDim.x + threadIdx.x;
    int t = idx >> 7, m = idx & 127;
    int r = (t * m) & (M_SIZE - 1);
    float s, c;
    sincospif((float)r * (1.0f / 2048.0f), &s, &c);
    __nv_bfloat16 ch, cl, sh, sl;
    split_bf16(c, ch, cl); split_bf16(-s, sh, sl);
    size_t b = (size_t)t * NC + 2 * m;
    *(__nv_bfloat162*)&g_basis_h[b] = __halves2bfloat162(ch, sh);
    *(__nv_bfloat162*)&g_basis_l[b] = __halves2bfloat162(cl, sl);
}
__global__ void k_basis_b() {   // [c][t]
    int idx = blockIdx.x * blockDim.x + threadIdx.x;
    int m = idx >> 12, t = idx & 4095;
    int r = (t * m) & (M_SIZE - 1);
    float s, c;
    sincospif((float)r * (1.0f / 2048.0f), &s, &c);
    __nv_bfloat16 ch, cl, sh, sl;
    split_bf16(c, ch, cl); split_bf16(-s, sh, sl);
    g_basisT_h[(size_t)(2*m)   * M_SIZE + t] = ch;
    g_basisT_h[(size_t)(2*m+1) * M_SIZE + t] = sh;
    g_basisT_l[(size_t)(2*m)   * M_SIZE + t] = cl;
    g_basisT_l[(size_t)(2*m+1) * M_SIZE + t] = sl;
}

// ---------------------------------------------------------------------------
// Weight transpose: w2[o][i][m] float2 -> planes [m][o][i] bf16 hi/lo.
// ---------------------------------------------------------------------------
__global__ void __launch_bounds__(256) k_wtransp(const float2* __restrict__ w2) {
    __shared__ float2 s[64][33];
    const int o  = blockIdx.z;
    const int i0 = blockIdx.x * 64;
    const int m0 = blockIdx.y * 32;
    const int tid = threadIdx.x;
#pragma unroll
    for (int j = 0; j < 8; j++) {
        int f = tid + j * 256;
        int ii = f >> 5, ml = f & 31;
        s[ii][ml] = w2[((size_t)o * CH + i0 + ii) * NMODES + m0 + ml];
    }
    __syncthreads();
#pragma unroll
    for (int j = 0; j < 2; j++) {
        int f = tid + j * 256;
        int ml = f >> 4, ig = (f & 15) * 4;
        float2 v0 = s[ig][ml], v1 = s[ig+1][ml], v2 = s[ig+2][ml], v3 = s[ig+3][ml];
        size_t dst = ((size_t)(m0 + ml) * CH + o) * CH + i0 + ig;
        __nv_bfloat16 h0,l0,h1,l1,h2,l2,h3,l3;
        split_bf16(v0.x,h0,l0); split_bf16(v1.x,h1,l1);
        split_bf16(v2.x,h2,l2); split_bf16(v3.x,h3,l3);
        *(uint2*)&gWre_h[dst] = pack4(h0,h1,h2,h3);
        *(uint2*)&gWre_l[dst] = pack4(l0,l1,l2,l3);
        split_bf16(v0.y,h0,l0); split_bf16(v1.y,h1,l1);
        split_bf16(v2.y,h2,l2); split_bf16(v3.y,h3,l3);
        *(uint2*)&gWim_h[dst] = pack4(h0,h1,h2,h3);
        *(uint2*)&gWim_l[dst] = pack4(l0,l1,l2,l3);
    }
}

// ---------------------------------------------------------------------------
// Forward DFT: xT[c][row] = sum_k x[row][k] * basisT[c][k]
// 256 threads; block 64x128; warp grid 2x4, warp tile 32x32; K-chunk 64.
// All operands via cp.async; epilogue emits bf16 hi/lo planes.
// ---------------------------------------------------------------------------
__global__ void __launch_bounds__(256, 2) k_fwd() {
    extern __shared__ char sm[];
    uint32_t sb = smem_u32(sm);
    const int tid = threadIdx.x, lane = tid & 31, wid = tid >> 5;
    const int wr = wid & 1, wc = wid >> 1;
    const int row0 = blockIdx.x * 64;
    const int c0   = blockIdx.y * 128;

    uint32_t offA[2], offB[2];
#pragma unroll
    for (int mf = 0; mf < 2; mf++)
        offA[mf] = (wr*32 + mf*16 + (lane & 15)) * 128 + (lane >> 4) * 16;
#pragma unroll
    for (int p = 0; p < 2; p++)
        offB[p] = (wc*32 + p*16 + ((lane >> 4) << 3) + (lane & 7)) * 128
                + ((lane >> 3) & 1) * 16;

    float acc[2][4][4];
#pragma unroll
    for (int i = 0; i < 2; i++)
#pragma unroll
        for (int j = 0; j < 4; j++)
#pragma unroll
            for (int q = 0; q < 4; q++) acc[i][j][q] = 0.0f;

    // loader: A (2 planes x 64 rows x 8cb) + B (2 planes x 128 rows x 8cb)
#define FWD_LOAD(dstb, kk) do {                                                   \
    _Pragma("unroll")                                                             \
    for (int j = 0; j < 4; j++) {                                                 \
        int f = tid + j * 256;                                                    \
        int plane = f >> 9, r = (f >> 3) & 63, cb = f & 7;                        \
        const __nv_bfloat16* src = (plane ? g_x_l : g_x_h)                        \
                                 + (size_t)(row0 + r) * M_SIZE + (kk) + cb * 8;   \
        CP16((dstb) + P_AH + plane * 8192 + SW(r * 128 + cb * 16), src);          \
    }                                                                             \
    _Pragma("unroll")                                                             \
    for (int j = 0; j < 8; j++) {                                                 \
        int f = tid + j * 256;                                                    \
        int plane = f >> 10, r = (f >> 3) & 127, cb = f & 7;                      \
        const __nv_bfloat16* src = (plane ? g_basisT_l : g_basisT_h)              \
                                 + (size_t)(c0 + r) * M_SIZE + (kk) + cb * 8;     \
        CP16((dstb) + P_BH + plane * 16384 + SW(r * 128 + cb * 16), src);         \
    }                                                                             \
    CP_COMMIT();                                                                  \
} while (0)

    FWD_LOAD(sb, 0);
    CP_WAIT0();
    __syncthreads();

    const int NCHUNK = M_SIZE / 64;
    for (int cc = 0; cc < NCHUNK; cc++) {
        uint32_t bb  = sb + (cc & 1) * BUFB;
        uint32_t nbb = sb + ((cc + 1) & 1) * BUFB;
        if (cc + 1 < NCHUNK) FWD_LOAD(nbb, (cc + 1) * 64);
#pragma unroll
        for (int ks = 0; ks < 4; ks++) {
            uint32_t Af[2][4], Bh[2][4], Bo[2][4];
#pragma unroll
            for (int mf = 0; mf < 2; mf++) LDSM4(Af[mf], bb + P_AH + SW(offA[mf] + ks * 32));
#pragma unroll
            for (int p = 0; p < 2; p++)    LDSM4(Bh[p],  bb + P_BH + SW(offB[p] + ks * 32));
#pragma unroll
            for (int mf = 0; mf < 2; mf++)
#pragma unroll
                for (int nf = 0; nf < 4; nf++)
                    MMA4(acc[mf][nf], Af[mf], Bh[nf>>1][(nf&1)*2], Bh[nf>>1][(nf&1)*2+1]);
#pragma unroll
            for (int p = 0; p < 2; p++)    LDSM4(Bo[p],  bb + P_BL + SW(offB[p] + ks * 32));
#pragma unroll
            for (int mf = 0; mf < 2; mf++)
#pragma unroll
                for (int nf = 0; nf < 4; nf++)
                    MMA4(acc[mf][nf], Af[mf], Bo[nf>>1][(nf&1)*2], Bo[nf>>1][(nf&1)*2+1]);
#pragma unroll
            for (int mf = 0; mf < 2; mf++) LDSM4(Af[mf], bb + P_AL + SW(offA[mf] + ks * 32));
#pragma unroll
            for (int mf = 0; mf < 2; mf++)
#pragma unroll
                for (int nf = 0; nf < 4; nf++)
                    MMA4(acc[mf][nf], Af[mf], Bh[nf>>1][(nf&1)*2], Bh[nf>>1][(nf&1)*2+1]);
        }
        CP_WAIT0();
        __syncthreads();
    }
#undef FWD_LOAD
    // ---- epilogue: split + write bf16 planes xT[c][row] ----
#pragma unroll
    for (int mf = 0; mf < 2; mf++) {
        int row = row0 + wr*32 + mf*16 + (lane >> 2);
#pragma unroll
        for (int nf = 0; nf < 4; nf++) {
            int col = c0 + wc*32 + nf*8 + (lane & 3) * 2;
#pragma unroll
            for (int q = 0; q < 4; q++) {
                int cc2 = col + (q & 1);
                int rr2 = row + (q >> 1) * 8;
                __nv_bfloat16 h, l;
                split_bf16(acc[mf][nf][q], h, l);
                g_xT_h[(size_t)cc2 * NROWS + rr2] = h;
                g_xT_l[(size_t)cc2 * NROWS + rr2] = l;
            }
        }
    }
}

// ---------------------------------------------------------------------------
// MMA mode mixing. CTA = (mode m, 64-wide o slice). M=32(b), N=64(o), K=256(i).
// Dual accumulators: re = S(XreWre) - S(XimWim); im = S(XreWim) + S(XimWre).
// A planes via cp.async (bf16 from k_fwd). Single W buffer, 96KB -> 2 CTAs/SM.
// ---------------------------------------------------------------------------
#define MX_REH 0
#define MX_REL 16384
#define MX_IMH 32768
#define MX_IML 49152
#define MW_BASE 65536
#define SMEM_MIX (MW_BASE + 32768)   // 96KB

__global__ void __launch_bounds__(256, 2) k_mixmma() {
    extern __shared__ char sm[];
    uint32_t sb = smem_u32(sm);
    const int tid = threadIdx.x, lane = tid & 31, wid = tid >> 5;
    const int wg = wid >> 2, wn = wid & 3;
    const int m  = blockIdx.x;
    const int o0 = blockIdx.y * 64;

#define MIX_LOADW(kk) do {                                                        \
    _Pragma("unroll")                                                             \
    for (int j = 0; j < 8; j++) {                                                 \
        int f = tid + j * 256;                                                    \
        int p = f >> 9, r = (f >> 3) & 63, cb = f & 7;                            \
        const __nv_bfloat16* src = (p == 0) ? gWre_h : (p == 1) ? gWre_l          \
                                 : (p == 2) ? gWim_h : gWim_l;                    \
        CP16(sb + MW_BASE + p * 8192 + SW(r * 128 + cb * 16),                     \
             src + ((size_t)m * CH + o0 + r) * CH + (kk) + cb * 8);               \
    }                                                                             \
    CP_COMMIT();                                                                  \
} while (0)

    // ---- A planes (all K) + W chunk 0 ----
    {
        const __nv_bfloat16* srcs[4] = {
            g_xT_h + (size_t)(2 * m)     * NROWS,
            g_xT_l + (size_t)(2 * m)     * NROWS,
            g_xT_h + (size_t)(2 * m + 1) * NROWS,
            g_xT_l + (size_t)(2 * m + 1) * NROWS };
#pragma unroll
        for (int j = 0; j < 16; j++) {
            int f = tid + j * 256;
            int p = f >> 10, rem = f & 1023;
            int b = rem >> 5, cb32 = rem & 31;
            int chunk = cb32 >> 3, cb = cb32 & 7;
            CP16(sb + p * 16384 + chunk * 4096 + SW(b * 128 + cb * 16),
                 srcs[p] + (size_t)b * CH + cb32 * 8);
        }
        MIX_LOADW(0);
        CP_WAIT0();
    }
    __syncthreads();

    uint32_t offA[2], offB;
#pragma unroll
    for (int mf = 0; mf < 2; mf++)
        offA[mf] = (mf*16 + (lane & 15)) * 128 + (lane >> 4) * 16;
    offB = (wn*16 + ((lane >> 4) << 3) + (lane & 7)) * 128 + ((lane >> 3) & 1) * 16;

    // B plane offsets: wg0 uses (Wre for acc1, Wim for acc2); wg1 swapped.
    const uint32_t b1 = wg ? 16384u : 0u;      // acc1: Wim : Wre
    const uint32_t b2 = wg ? 0u : 16384u;      // acc2: Wre : Wim

    float acc1[2][2][4], acc2[2][2][4];
#pragma unroll
    for (int i = 0; i < 2; i++)
#pragma unroll
        for (int j = 0; j < 2; j++)
#pragma unroll
            for (int q = 0; q < 4; q++) { acc1[i][j][q] = 0.0f; acc2[i][j][q] = 0.0f; }

    for (int cc = 0; cc < 4; cc++) {
        uint32_t wb = sb + MW_BASE;
#pragma unroll
        for (int ks = 0; ks < 4; ks++) {
#pragma unroll
            for (int combo = 0; combo < 2; combo++) {
                // combo0: A=Xre -> acc1 with b1 ; combo1: A=Xim -> acc2 with b2
                uint32_t ah = sb + (combo ? MX_IMH : MX_REH) + cc * 4096;
                uint32_t al = sb + (combo ? MX_IML : MX_REL) + cc * 4096;
                uint32_t bbx = wb + (combo ? b2 : b1);
                float (*acc)[2][4] = combo ? acc2 : acc1;
                uint32_t Ah[2][4], Al[2][4], Bh[4], Bl[4];
#pragma unroll
                for (int mf = 0; mf < 2; mf++) {
                    LDSM4(Ah[mf], ah + SW(offA[mf] + ks * 32));
                    LDSM4(Al[mf], al + SW(offA[mf] + ks * 32));
                }
                LDSM4(Bh, bbx + SW(offB + ks * 32));
                LDSM4(Bl, bbx + 8192 + SW(offB + ks * 32));
#pragma unroll
                for (int mf = 0; mf < 2; mf++)
#pragma unroll
                    for (int nf = 0; nf < 2; nf++) {
                        MMA4(acc[mf][nf], Ah[mf], Bh[nf*2], Bh[nf*2+1]);
                        MMA4(acc[mf][nf], Al[mf], Bh[nf*2], Bh[nf*2+1]);
                        MMA4(acc[mf][nf], Ah[mf], Bl[nf*2], Bl[nf*2+1]);
                    }
            }
        }
        __syncthreads();
        if (cc + 1 < 4) {
            MIX_LOADW((cc + 1) * 64);
            CP_WAIT0();
            __syncthreads();
        }
    }
#undef MIX_LOADW

    // ---- epilogue: combine, scale, split, store ----
    const float sgn = wg ? 1.0f : -1.0f;
    const float sc = (m == 0 ? 1.0f : 2.0f) * (1.0f / (float)M_SIZE);
    const int cidx = 2 * m + wg;
#pragma unroll
    for (int mf = 0; mf < 2; mf++) {
#pragma unroll
        for (int nf = 0; nf < 2; nf++) {
#pragma unroll
            for (int h = 0; h < 2; h++) {
                int b  = mf*16 + (lane >> 2) + h * 8;
                int oo = o0 + wn*16 + nf*8 + (lane & 3) * 2;
                float v0 = (acc1[mf][nf][h*2]     + sgn * acc2[mf][nf][h*2])     * sc;
                float v1 = (acc1[mf][nf][h*2 + 1] + sgn * acc2[mf][nf][h*2 + 1]) * sc;
                __nv_bfloat16 hh, ll;
                size_t i0 = ((size_t)b * CH + oo) * NC + cidx;
                split_bf16(v0, hh, ll); g_oft_h[i0] = hh; g_oft_l[i0] = ll;
                size_t i1 = ((size_t)b * CH + oo + 1) * NC + cidx;
                split_bf16(v1, hh, ll); g_oft_h[i1] = hh; g_oft_l[i1] = ll;
            }
        }
    }
}

// ---------------------------------------------------------------------------
// Inverse DFT + LeakyReLU + residual. (R8-proven)
// 256 threads; block 64 rows x 128 t; warp grid 2x4, warp tile 32x32.
// ---------------------------------------------------------------------------
__global__ void __launch_bounds__(256, 2) k_inv(const float* __restrict__ x,
                                                float* __restrict__ out) {
    extern __shared__ char sm[];
    uint32_t sb = smem_u32(sm);
    const int tid = threadIdx.x, lane = tid & 31, wid = tid >> 5;
    const int wr = wid & 1, wc = wid >> 1;
    const int t0   = blockIdx.x * 128;
    const int row0 = blockIdx.y * 64;

    uint32_t offA[2], offB[2];
#pragma unroll
    for (int mf = 0; mf < 2; mf++)
        offA[mf] = (wr*32 + mf*16 + (lane & 15)) * 128 + (lane >> 4) * 16;
#pragma unroll
    for (int p = 0; p < 2; p++)
        offB[p] = (wc*32 + p*16 + ((lane >> 4) << 3) + (lane & 7)) * 128
                + ((lane >> 3) & 1) * 16;

    float acc[2][4][4];
#pragma unroll
    for (int i = 0; i < 2; i++)
#pragma unroll
        for (int j = 0; j < 4; j++)
#pragma unroll
            for (int q = 0; q < 4; q++) acc[i][j][q] = 0.0f;

#define INV_LOAD(dstb, kk) do {                                                   \
    _Pragma("unroll")                                                             \
    for (int j = 0; j < 4; j++) {                                                 \
        int f = tid + j * 256;                                                    \
        int plane = f >> 9, r = (f >> 3) & 63, cb = f & 7;                        \
        const __nv_bfloat16* src = (plane ? g_oft_l : g_oft_h)                    \
                                 + (size_t)(row0 + r) * NC + (kk) + cb * 8;       \
        CP16((dstb) + P_AH + plane * 8192 + SW(r * 128 + cb * 16), src);          \
    }                                                                             \
    _Pragma("unroll")                                                             \
    for (int j = 0; j < 8; j++) {                                                 \
        int f = tid + j * 256;                                                    \
        int plane = f >> 10, r = (f >> 3) & 127, cb = f & 7;                      \
        const __nv_bfloat16* src = (plane ? g_basis_l : g_basis_h)                \
                                 + (size_t)(t0 + r) * NC + (kk) + cb * 8;         \
        CP16((dstb) + P_BH + plane * 16384 + SW(r * 128 + cb * 16), src);         \
    }                                                                             \
    CP_COMMIT();                                                                  \
} while (0)

    INV_LOAD(sb, 0);
    CP_WAIT0();
    __syncthreads();

    const int NCHUNK = NC / 64;
    for (int cc = 0; cc < NCHUNK; cc++) {
        uint32_t bb  = sb + (cc & 1) * BUFB;
        uint32_t nbb = sb + ((cc + 1) & 1) * BUFB;
        if (cc + 1 < NCHUNK) INV_LOAD(nbb, (cc + 1) * 64);
#pragma unroll
        for (int ks = 0; ks < 4; ks++) {
            uint32_t Af[2][4], Bh[2][4], Bo[2][4];
#pragma unroll
            for (int mf = 0; mf < 2; mf++) LDSM4(Af[mf], bb + P_AH + SW(offA[mf] + ks * 32));
#pragma unroll
            for (int p = 0; p < 2; p++)    LDSM4(Bh[p],  bb + P_BH + SW(offB[p] + ks * 32));
#pragma unroll
            for (int mf = 0; mf < 2; mf++)
#pragma unroll
                for (int nf = 0; nf < 4; nf++)
                    MMA4(acc[mf][nf], Af[mf], Bh[nf>>1][(nf&1)*2], Bh[nf>>1][(nf&1)*2+1]);
#pragma unroll
            for (int p = 0; p < 2; p++)    LDSM4(Bo[p],  bb + P_BL + SW(offB[p] + ks * 32));
#pragma unroll
            for (int mf = 0; mf < 2; mf++)
#pragma unroll
                for (int nf = 0; nf < 4; nf++)
                    MMA4(acc[mf][nf], Af[mf], Bo[nf>>1][(nf&1)*2], Bo[nf>>1][(nf&1)*2+1]);
#pragma unroll
            for (int mf = 0; mf < 2; mf++) LDSM4(Af[mf], bb + P_AL + SW(offA[mf] + ks * 32));
#pragma unroll
            for (int mf = 0; mf < 2; mf++)
#pragma unroll
                for (int nf = 0; nf < 4; nf++)
                    MMA4(acc[mf][nf], Af[mf], Bh[nf>>1][(nf&1)*2], Bh[nf>>1][(nf&1)*2+1]);
        }
        CP_WAIT0();
        __syncthreads();
    }
#undef INV_LOAD
#pragma unroll
    for (int mf = 0; mf < 2; mf++) {
        int row = row0 + wr*32 + mf*16 + (lane >> 2);
#pragma unroll
        for (int nf = 0; nf < 4; nf++) {
            int tc = t0 + wc*32 + nf*8 + (lane & 3) * 2;
#pragma unroll
            for (int h = 0; h < 2; h++) {
                size_t base = (size_t)(row + h * 8) * M_SIZE + tc;
                float2 xv = *(const float2*)&x[base];
                float v0 = acc[mf][nf][h*2], v1 = acc[mf][nf][h*2+1];
                float2 rv;
                rv.x = xv.x + (v0 >= 0.f ? v0 : 0.2f * v0);
                rv.y = xv.y + (v1 >= 0.f ? v1 : 0.2f * v1);
                *(float2*)&out[base] = rv;
            }
        }
    }
}

// ---------------------------------------------------------------------------
extern "C" void kernel_launch(void* const* d_in, const int* in_sizes, int n_in,
                              void* d_out, int out_size) {
    (void)in_sizes; (void)n_in; (void)out_size;
    const float*  x  = (const float*)d_in[0];
    const float2* w2 = (const float2*)d_in[1];
    float* out = (float*)d_out;

    cudaFuncSetAttribute(k_fwd,    cudaFuncAttributeMaxDynamicSharedMemorySize, SMEM_GEMM);
    cudaFuncSetAttribute(k_inv,    cudaFuncAttributeMaxDynamicSharedMemorySize, SMEM_GEMM);
    cudaFuncSetAttribute(k_mixmma, cudaFuncAttributeMaxDynamicSharedMemorySize, SMEM_MIX);

    k_xsplit<<<(NROWS * M_SIZE) / 1024, 256>>>(x);
    k_basis_a<<<(M_SIZE * NMODES) / 256, 256>>>();
    k_basis_b<<<(M_SIZE * NMODES) / 256, 256>>>();
    k_wtransp<<<dim3(CH / 64, NMODES / 32, CH), 256>>>(w2);
    k_fwd<<<dim3(NROWS / 64, NC / 128), 256, SMEM_GEMM>>>();
    k_mixmma<<<dim3(NMODES, CH / 64), 256, SMEM_MIX>>>();
    k_inv<<<dim3(M_SIZE / 128, NROWS / 64), 256, SMEM_GEMM>>>(x, out);
}